// round 8
// baseline (speedup 1.0000x reference)
#include <cuda_runtime.h>
#include <cuda_bf16.h>
#include <cstdint>

#define NN 100000
#define NE 800000
#define HD 128
#define ED 32
#define KZ 288   // Z row: [s(128) | deg*x(128) | sum_ea(32)]
#define SK 40    // smem row stride in halfs (conflict-free for ldmatrix)
#define TILEH (128 * SK)          // halfs per tile (one stage)
#define SMEM_GEMM (8 * TILEH * 2 + 512)  // 4 arrays x 2 stages x bytes + bias

// ---------------- device scratch (static, no allocations) ----------------
__device__ int   g_is64;
__device__ int   g_deg[NN];
__device__ int   g_rowptr[NN + 1];
__device__ int   g_cursor[NN];
__device__ int   g_bsum[128];
__device__ int   g_col[NE];
__device__ int   g_eid[NE];
__device__ float g_degf[NN];
__device__ __align__(16) __nv_bfloat16 g_Zh[(size_t)NN * KZ];
__device__ __align__(16) __nv_bfloat16 g_Zl[(size_t)NN * KZ];
__device__ __align__(16) __nv_bfloat16 g_Wh[3 * HD * KZ];
__device__ __align__(16) __nv_bfloat16 g_Wl[3 * HD * KZ];
__device__ __align__(16) float g_X1[(size_t)NN * HD];
__device__ __align__(16) float g_X2[(size_t)NN * HD];

// ---------------- helpers ----------------
__device__ __forceinline__ int edge_val(const void* ei, int idx) {
    if (g_is64) return (int)((const long long*)ei)[idx];
    return ((const int*)ei)[idx];
}

__device__ __forceinline__ void split2(float v, __nv_bfloat16& h, __nv_bfloat16& l) {
    h = __float2bfloat16(v);
    l = __float2bfloat16(v - __bfloat162float(h));
}

__device__ __forceinline__ uint32_t pk(__nv_bfloat16 a, __nv_bfloat16 b) {
    __nv_bfloat162 t(a, b);
    return *reinterpret_cast<uint32_t*>(&t);
}

__device__ __forceinline__ void ldsm4(uint32_t* r, const void* p) {
    uint32_t a = (uint32_t)__cvta_generic_to_shared(p);
    asm volatile("ldmatrix.sync.aligned.m8n8.x4.shared.b16 {%0,%1,%2,%3}, [%4];\n"
        : "=r"(r[0]), "=r"(r[1]), "=r"(r[2]), "=r"(r[3]) : "r"(a));
}

__device__ __forceinline__ void mma16816(float* d, const uint32_t* a, const uint32_t* b) {
    asm volatile(
        "mma.sync.aligned.m16n8k16.row.col.f32.bf16.bf16.f32 "
        "{%0,%1,%2,%3}, {%4,%5,%6,%7}, {%8,%9}, {%0,%1,%2,%3};\n"
        : "+f"(d[0]), "+f"(d[1]), "+f"(d[2]), "+f"(d[3])
        : "r"(a[0]), "r"(a[1]), "r"(a[2]), "r"(a[3]), "r"(b[0]), "r"(b[1]));
}

__device__ __forceinline__ void cpa16(void* smem, const void* g, int sz) {
    uint32_t a = (uint32_t)__cvta_generic_to_shared(smem);
    asm volatile("cp.async.cg.shared.global [%0], [%1], 16, %2;\n"
        :: "r"(a), "l"(g), "r"(sz));
}

__device__ __forceinline__ void stcs2(void* p, uint2 v) {
    asm volatile("st.global.cs.v2.b32 [%0], {%1,%2};\n" :: "l"(p), "r"(v.x), "r"(v.y));
}

// ---------------- dtype detect ----------------
__global__ void k_detect(const int* __restrict__ p) {
    int odd_nonzero = 0;
    for (int i = 1; i < 128; i += 2)
        if (p[i] != 0) odd_nonzero++;
    g_is64 = (odd_nonzero == 0) ? 1 : 0;
}

// ---------------- one-time W split ----------------
__global__ void k_wsplit(const float* __restrict__ Wm) {
    int i = blockIdx.x * blockDim.x + threadIdx.x;
    if (i < 3 * HD * KZ) {
        __nv_bfloat16 h, l;
        split2(Wm[i], h, l);
        g_Wh[i] = h;
        g_Wl[i] = l;
    }
}

// ---------------- CSR build ----------------
__global__ void k_zero_deg() {
    int i = blockIdx.x * blockDim.x + threadIdx.x;
    if (i < NN) g_deg[i] = 0;
}

__global__ void k_hist(const void* __restrict__ ei) {
    int e = blockIdx.x * blockDim.x + threadIdx.x;
    if (e < NE) {
        int dst = edge_val(ei, NE + e);
        if ((unsigned)dst < NN) atomicAdd(&g_deg[dst], 1);
    }
}

__global__ void k_scan1() {
    __shared__ int sh[1024];
    int tid = threadIdx.x;
    int i = blockIdx.x * 1024 + tid;
    int v = (i < NN) ? g_deg[i] : 0;
    sh[tid] = v;
    __syncthreads();
    #pragma unroll
    for (int off = 1; off < 1024; off <<= 1) {
        int t = (tid >= off) ? sh[tid - off] : 0;
        __syncthreads();
        sh[tid] += t;
        __syncthreads();
    }
    if (i < NN) g_rowptr[i + 1] = sh[tid];
    if (tid == 1023) g_bsum[blockIdx.x] = sh[1023];
}

__global__ void k_scan2(int nblk) {
    int acc = 0;
    for (int b = 0; b < nblk; b++) {
        int t = g_bsum[b];
        g_bsum[b] = acc;
        acc += t;
    }
}

__global__ void k_scan3() {
    int i = blockIdx.x * blockDim.x + threadIdx.x;
    if (i < NN) {
        int incl = g_rowptr[i + 1] + g_bsum[i >> 10];
        g_rowptr[i + 1] = incl;
        g_cursor[i] = incl - g_deg[i];
    }
    if (i == 0) g_rowptr[0] = 0;
}

__global__ void k_fill(const void* __restrict__ ei) {
    int e = blockIdx.x * blockDim.x + threadIdx.x;
    if (e < NE) {
        int src = edge_val(ei, e);
        int dst = edge_val(ei, NE + e);
        if ((unsigned)src >= NN || (unsigned)dst >= NN) return;
        int p = atomicAdd(&g_cursor[dst], 1);
        g_col[p] = src;
        g_eid[p] = e;
    }
}

// per-node: sort row by eid (deterministic), degf, Zh/Zl[:,256:288] = sum edge_attr
__global__ void k_pre(const float* __restrict__ ea) {
    int gid  = blockIdx.x * blockDim.x + threadIdx.x;
    int node = gid >> 5;
    int lane = gid & 31;
    if (node >= NN) return;
    int s = g_rowptr[node], e = g_rowptr[node + 1];
    if (lane == 0) {
        for (int i = s + 1; i < e; i++) {
            int ke = g_eid[i], kc = g_col[i];
            int j = i - 1;
            while (j >= s && g_eid[j] > ke) {
                g_eid[j + 1] = g_eid[j];
                g_col[j + 1] = g_col[j];
                j--;
            }
            g_eid[j + 1] = ke;
            g_col[j + 1] = kc;
        }
        g_degf[node] = (float)(e - s);
    }
    __syncwarp();
    float acc = 0.f;
    for (int p = s; p < e; p++)
        acc += ea[(size_t)g_eid[p] * ED + lane];
    __nv_bfloat16 h, l;
    split2(acc, h, l);
    g_Zh[(size_t)node * KZ + 256 + lane] = h;
    g_Zl[(size_t)node * KZ + 256 + lane] = l;
}

// ---------------- per-layer SpMM -> split-bf16 Z (2-way MLP, streaming stores)
__global__ void k_spmm(const float* __restrict__ xext, int sel) {
    int gid  = blockIdx.x * blockDim.x + threadIdx.x;
    int node = gid >> 5;
    int lane = gid & 31;
    if (node >= NN) return;
    const float* xin = (sel == 0) ? xext : (sel == 1 ? g_X1 : g_X2);
    const float4* __restrict__ X4 = (const float4*)xin;
    int s = g_rowptr[node], e = g_rowptr[node + 1];
    float4 a0 = make_float4(0.f, 0.f, 0.f, 0.f);
    float4 a1 = make_float4(0.f, 0.f, 0.f, 0.f);
    int p = s;
    for (; p + 1 < e; p += 2) {
        int c0 = g_col[p], c1 = g_col[p + 1];
        float4 v0 = X4[(size_t)c0 * 32 + lane];
        float4 v1 = X4[(size_t)c1 * 32 + lane];
        a0.x += v0.x; a0.y += v0.y; a0.z += v0.z; a0.w += v0.w;
        a1.x += v1.x; a1.y += v1.y; a1.z += v1.z; a1.w += v1.w;
    }
    if (p < e) {
        int c0 = g_col[p];
        float4 v0 = X4[(size_t)c0 * 32 + lane];
        a0.x += v0.x; a0.y += v0.y; a0.z += v0.z; a0.w += v0.w;
    }
    float4 acc = make_float4(a0.x + a1.x, a0.y + a1.y, a0.z + a1.z, a0.w + a1.w);

    __nv_bfloat16 h0, h1, h2, h3, l0, l1, l2, l3;
    split2(acc.x, h0, l0); split2(acc.y, h1, l1);
    split2(acc.z, h2, l2); split2(acc.w, h3, l3);
    size_t base = (size_t)node * KZ + lane * 4;
    stcs2(&g_Zh[base], make_uint2(pk(h0, h1), pk(h2, h3)));
    stcs2(&g_Zl[base], make_uint2(pk(l0, l1), pk(l2, l3)));

    float dg = g_degf[node];
    float4 xv = X4[(size_t)node * 32 + lane];
    split2(dg * xv.x, h0, l0); split2(dg * xv.y, h1, l1);
    split2(dg * xv.z, h2, l2); split2(dg * xv.w, h3, l3);
    size_t base2 = (size_t)node * KZ + 128 + lane * 4;
    stcs2(&g_Zh[base2], make_uint2(pk(h0, h1), pk(h2, h3)));
    stcs2(&g_Zl[base2], make_uint2(pk(l0, l1), pk(l2, l3)));
}

// ---------------- per-layer GEMM: Y = leaky(Z @ W^T + deg*b), bf16-split mma,
// cp.async 2-stage pipeline. BM=128, BN=128, BK=32, 8 warps (4m x 2n).
__global__ __launch_bounds__(256) void k_gemm(
    int layer, const float* __restrict__ bvec,
    float* __restrict__ oext, int osel, int last)
{
    extern __shared__ char smemraw[];
    __nv_bfloat16* Ah = (__nv_bfloat16*)smemraw;       // [2][TILEH]
    __nv_bfloat16* Al = Ah + 2 * TILEH;
    __nv_bfloat16* Bh = Al + 2 * TILEH;
    __nv_bfloat16* Bl = Bh + 2 * TILEH;
    float* sb = (float*)(Bl + 2 * TILEH);

    const __nv_bfloat16* Wh = g_Wh + (size_t)layer * HD * KZ;
    const __nv_bfloat16* Wl = g_Wl + (size_t)layer * HD * KZ;

    int t = threadIdx.x;
    int lane = t & 31, wid = t >> 5;
    int wm = wid >> 1, wn = wid & 1;
    int m0 = blockIdx.x * 128;
    float* out = (osel == 3) ? oext : (osel == 1 ? g_X1 : g_X2);
    if (t < 128) sb[t] = bvec[t];

    float c[2][8][4];
    #pragma unroll
    for (int a = 0; a < 2; a++)
        #pragma unroll
        for (int b = 0; b < 8; b++)
            #pragma unroll
            for (int d = 0; d < 4; d++) c[a][b][d] = 0.f;

    // stage copy: 512 fragments of 16B per array
    auto stage_copy = [&](int st, int k0) {
        #pragma unroll
        for (int h = 0; h < 2; h++) {
            int fid = t + h * 256;
            int row = fid >> 2, cc = fid & 3;
            int m = m0 + row;
            int off = st * TILEH + row * SK + cc * 8;
            bool v = (m < NN);
            const __nv_bfloat16* pa = v ? &g_Zh[(size_t)m * KZ + k0 + cc * 8] : g_Zh;
            const __nv_bfloat16* pl = v ? &g_Zl[(size_t)m * KZ + k0 + cc * 8] : g_Zl;
            cpa16(&Ah[off], pa, v ? 16 : 0);
            cpa16(&Al[off], pl, v ? 16 : 0);
            cpa16(&Bh[off], &Wh[(size_t)row * KZ + k0 + cc * 8], 16);
            cpa16(&Bl[off], &Wl[(size_t)row * KZ + k0 + cc * 8], 16);
        }
    };

    stage_copy(0, 0);
    asm volatile("cp.async.commit_group;\n");

    for (int i = 0; i < 9; i++) {
        if (i < 8) {
            stage_copy((i + 1) & 1, (i + 1) * 32);
            asm volatile("cp.async.commit_group;\n");
            asm volatile("cp.async.wait_group 1;\n");
        } else {
            asm volatile("cp.async.wait_group 0;\n");
        }
        __syncthreads();
        int st = i & 1;
        int sb0 = st * TILEH;
        #pragma unroll
        for (int kk = 0; kk < 2; kk++) {
            uint32_t ah[2][4], al[2][4];
            #pragma unroll
            for (int mt = 0; mt < 2; mt++) {
                int r = wm * 32 + mt * 16 + (lane & 15);
                int kc = kk * 16 + ((lane >> 4) << 3);
                ldsm4(ah[mt], &Ah[sb0 + r * SK + kc]);
                ldsm4(al[mt], &Al[sb0 + r * SK + kc]);
            }
            #pragma unroll
            for (int p = 0; p < 4; p++) {
                int nr = wn * 64 + p * 16 + (lane & 7) + ((lane >> 4) << 3);
                int kc = kk * 16 + (((lane >> 3) & 1) << 3);
                uint32_t bh[4], bl[4];
                ldsm4(bh, &Bh[sb0 + nr * SK + kc]);
                ldsm4(bl, &Bl[sb0 + nr * SK + kc]);
                #pragma unroll
                for (int mt = 0; mt < 2; mt++) {
                    mma16816(c[mt][2 * p],     ah[mt], bh);
                    mma16816(c[mt][2 * p + 1], ah[mt], bh + 2);
                    mma16816(c[mt][2 * p],     ah[mt], bl);
                    mma16816(c[mt][2 * p + 1], ah[mt], bl + 2);
                    mma16816(c[mt][2 * p],     al[mt], bh);
                    mma16816(c[mt][2 * p + 1], al[mt], bh + 2);
                }
            }
        }
        __syncthreads();
    }

    // epilogue: y = c + deg*b, leaky (x2 if last)
    #pragma unroll
    for (int mt = 0; mt < 2; mt++) {
        int r0 = m0 + wm * 32 + mt * 16 + (lane >> 2);
        int r1 = r0 + 8;
        float dg0 = (r0 < NN) ? g_degf[r0] : 0.f;
        float dg1 = (r1 < NN) ? g_degf[r1] : 0.f;
        #pragma unroll
        for (int nt = 0; nt < 8; nt++) {
            int col = wn * 64 + nt * 8 + ((lane & 3) << 1);
            float b0 = sb[col], b1 = sb[col + 1];
            if (r0 < NN) {
                float y0 = c[mt][nt][0] + dg0 * b0;
                float y1 = c[mt][nt][1] + dg0 * b1;
                y0 = y0 > 0.f ? y0 : 0.01f * y0;
                y1 = y1 > 0.f ? y1 : 0.01f * y1;
                if (last) {
                    y0 = y0 > 0.f ? y0 : 0.01f * y0;
                    y1 = y1 > 0.f ? y1 : 0.01f * y1;
                }
                *(float2*)&out[(size_t)r0 * HD + col] = make_float2(y0, y1);
            }
            if (r1 < NN) {
                float y2 = c[mt][nt][2] + dg1 * b0;
                float y3 = c[mt][nt][3] + dg1 * b1;
                y2 = y2 > 0.f ? y2 : 0.01f * y2;
                y3 = y3 > 0.f ? y3 : 0.01f * y3;
                if (last) {
                    y2 = y2 > 0.f ? y2 : 0.01f * y2;
                    y3 = y3 > 0.f ? y3 : 0.01f * y3;
                }
                *(float2*)&out[(size_t)r1 * HD + col] = make_float2(y2, y3);
            }
        }
    }
}

// ---------------- launch ----------------
extern "C" void kernel_launch(void* const* d_in, const int* in_sizes, int n_in,
                              void* d_out, int out_size) {
    const float* x  = nullptr;
    const void*  ei = nullptr;
    const float* ea = nullptr;
    const float* Wm = nullptr;
    const float* bm = nullptr;
    for (int i = 0; i < n_in; i++) {
        switch (in_sizes[i]) {
            case 12800000: x  = (const float*)d_in[i]; break;
            case 1600000:  ei = d_in[i];               break;
            case 25600000: ea = (const float*)d_in[i]; break;
            case 110592:   Wm = (const float*)d_in[i]; break;
            case 384:      bm = (const float*)d_in[i]; break;
            default: break;
        }
    }
    float* out = (float*)d_out;

    cudaFuncSetAttribute(k_gemm, cudaFuncAttributeMaxDynamicSharedMemorySize,
                         SMEM_GEMM);

    const int nblk = (NN + 1023) / 1024;   // 98
    k_detect<<<1, 1>>>((const int*)ei);
    k_zero_deg<<<(NN + 255) / 256, 256>>>();
    k_hist<<<(NE + 255) / 256, 256>>>(ei);
    k_scan1<<<nblk, 1024>>>();
    k_scan2<<<1, 1>>>(nblk);
    k_scan3<<<(NN + 255) / 256, 256>>>();
    k_fill<<<(NE + 255) / 256, 256>>>(ei);
    k_pre<<<(NN * 32 + 255) / 256, 256>>>(ea);
    k_wsplit<<<(3 * HD * KZ + 255) / 256, 256>>>(Wm);

    const int gemm_blocks = (NN + 127) / 128;   // 782
    // layer 0: in = x,    out = g_X1
    k_spmm<<<(NN * 32 + 255) / 256, 256>>>(x, 0);
    k_gemm<<<gemm_blocks, 256, SMEM_GEMM>>>(0, bm + 0 * HD, out, 1, 0);
    // layer 1: in = g_X1, out = g_X2
    k_spmm<<<(NN * 32 + 255) / 256, 256>>>(nullptr, 1);
    k_gemm<<<gemm_blocks, 256, SMEM_GEMM>>>(1, bm + 1 * HD, out, 2, 0);
    // layer 2: in = g_X2, out = d_out (double leaky: activate_last)
    k_spmm<<<(NN * 32 + 255) / 256, 256>>>(nullptr, 2);
    k_gemm<<<gemm_blocks, 256, SMEM_GEMM>>>(2, bm + 2 * HD, out, 3, 1);
}

// round 9
// speedup vs baseline: 1.0416x; 1.0416x over previous
#include <cuda_runtime.h>
#include <cuda_bf16.h>
#include <cstdint>

#define NN 100000
#define NE 800000
#define HD 128
#define ED 32
#define KZ 288   // Z row: [s(128) | deg*x(128) | sum_ea(32)]
#define SK 40    // smem row stride in halfs (conflict-free for ldmatrix)

// ---------------- device scratch (static, no allocations) ----------------
__device__ int   g_is64;
__device__ int   g_deg[NN];
__device__ int   g_rowptr[NN + 1];
__device__ int   g_cursor[NN];
__device__ int   g_bsum[128];
__device__ int   g_col[NE];
__device__ int   g_eid[NE];
__device__ float g_degf[NN];
__device__ __align__(16) __nv_bfloat16 g_Zh[(size_t)NN * KZ];
__device__ __align__(16) __nv_bfloat16 g_Zl[(size_t)NN * KZ];
__device__ __align__(16) __nv_bfloat16 g_Wh[3 * HD * KZ];
__device__ __align__(16) __nv_bfloat16 g_Wl[3 * HD * KZ];
__device__ __align__(16) float g_X1[(size_t)NN * HD];
__device__ __align__(16) float g_X2[(size_t)NN * HD];

// ---------------- helpers ----------------
__device__ __forceinline__ int edge_val(const void* ei, int idx) {
    if (g_is64) return (int)((const long long*)ei)[idx];
    return ((const int*)ei)[idx];
}

__device__ __forceinline__ void split2(float v, __nv_bfloat16& h, __nv_bfloat16& l) {
    h = __float2bfloat16(v);
    l = __float2bfloat16(v - __bfloat162float(h));
}

__device__ __forceinline__ uint32_t pk(__nv_bfloat16 a, __nv_bfloat16 b) {
    __nv_bfloat162 t(a, b);
    return *reinterpret_cast<uint32_t*>(&t);
}

__device__ __forceinline__ void ldsm4(uint32_t* r, const void* p) {
    uint32_t a = (uint32_t)__cvta_generic_to_shared(p);
    asm volatile("ldmatrix.sync.aligned.m8n8.x4.shared.b16 {%0,%1,%2,%3}, [%4];\n"
        : "=r"(r[0]), "=r"(r[1]), "=r"(r[2]), "=r"(r[3]) : "r"(a));
}

__device__ __forceinline__ void mma16816(float* d, const uint32_t* a, const uint32_t* b) {
    asm volatile(
        "mma.sync.aligned.m16n8k16.row.col.f32.bf16.bf16.f32 "
        "{%0,%1,%2,%3}, {%4,%5,%6,%7}, {%8,%9}, {%0,%1,%2,%3};\n"
        : "+f"(d[0]), "+f"(d[1]), "+f"(d[2]), "+f"(d[3])
        : "r"(a[0]), "r"(a[1]), "r"(a[2]), "r"(a[3]), "r"(b[0]), "r"(b[1]));
}

// ---------------- dtype detect ----------------
__global__ void k_detect(const int* __restrict__ p) {
    int odd_nonzero = 0;
    for (int i = 1; i < 128; i += 2)
        if (p[i] != 0) odd_nonzero++;
    g_is64 = (odd_nonzero == 0) ? 1 : 0;
}

// ---------------- one-time W split ----------------
__global__ void k_wsplit(const float* __restrict__ Wm) {
    int i = blockIdx.x * blockDim.x + threadIdx.x;
    if (i < 3 * HD * KZ) {
        __nv_bfloat16 h, l;
        split2(Wm[i], h, l);
        g_Wh[i] = h;
        g_Wl[i] = l;
    }
}

// ---------------- CSR build ----------------
__global__ void k_zero_deg() {
    int i = blockIdx.x * blockDim.x + threadIdx.x;
    if (i < NN) g_deg[i] = 0;
}

__global__ void k_hist(const void* __restrict__ ei) {
    int e = blockIdx.x * blockDim.x + threadIdx.x;
    if (e < NE) {
        int dst = edge_val(ei, NE + e);
        if ((unsigned)dst < NN) atomicAdd(&g_deg[dst], 1);
    }
}

__global__ void k_scan1() {
    __shared__ int sh[1024];
    int tid = threadIdx.x;
    int i = blockIdx.x * 1024 + tid;
    int v = (i < NN) ? g_deg[i] : 0;
    sh[tid] = v;
    __syncthreads();
    #pragma unroll
    for (int off = 1; off < 1024; off <<= 1) {
        int t = (tid >= off) ? sh[tid - off] : 0;
        __syncthreads();
        sh[tid] += t;
        __syncthreads();
    }
    if (i < NN) g_rowptr[i + 1] = sh[tid];
    if (tid == 1023) g_bsum[blockIdx.x] = sh[1023];
}

__global__ void k_scan2(int nblk) {
    int acc = 0;
    for (int b = 0; b < nblk; b++) {
        int t = g_bsum[b];
        g_bsum[b] = acc;
        acc += t;
    }
}

__global__ void k_scan3() {
    int i = blockIdx.x * blockDim.x + threadIdx.x;
    if (i < NN) {
        int incl = g_rowptr[i + 1] + g_bsum[i >> 10];
        g_rowptr[i + 1] = incl;
        g_cursor[i] = incl - g_deg[i];
    }
    if (i == 0) g_rowptr[0] = 0;
}

__global__ void k_fill(const void* __restrict__ ei) {
    int e = blockIdx.x * blockDim.x + threadIdx.x;
    if (e < NE) {
        int src = edge_val(ei, e);
        int dst = edge_val(ei, NE + e);
        if ((unsigned)src >= NN || (unsigned)dst >= NN) return;
        int p = atomicAdd(&g_cursor[dst], 1);
        g_col[p] = src;
        g_eid[p] = e;
    }
}

// per-node: sort row by eid (deterministic), degf, Zh/Zl[:,256:288] = sum edge_attr
__global__ void k_pre(const float* __restrict__ ea) {
    int gid  = blockIdx.x * blockDim.x + threadIdx.x;
    int node = gid >> 5;
    int lane = gid & 31;
    if (node >= NN) return;
    int s = g_rowptr[node], e = g_rowptr[node + 1];
    if (lane == 0) {
        for (int i = s + 1; i < e; i++) {
            int ke = g_eid[i], kc = g_col[i];
            int j = i - 1;
            while (j >= s && g_eid[j] > ke) {
                g_eid[j + 1] = g_eid[j];
                g_col[j + 1] = g_col[j];
                j--;
            }
            g_eid[j + 1] = ke;
            g_col[j + 1] = kc;
        }
        g_degf[node] = (float)(e - s);
    }
    __syncwarp();
    float acc = 0.f;
    for (int p = s; p < e; p++)
        acc += ea[(size_t)g_eid[p] * ED + lane];
    __nv_bfloat16 h, l;
    split2(acc, h, l);
    g_Zh[(size_t)node * KZ + 256 + lane] = h;
    g_Zl[(size_t)node * KZ + 256 + lane] = l;
}

// ---------------- per-layer SpMM -> split-bf16 Z (2-way MLP, NORMAL stores)
__global__ void k_spmm(const float* __restrict__ xext, int sel) {
    int gid  = blockIdx.x * blockDim.x + threadIdx.x;
    int node = gid >> 5;
    int lane = gid & 31;
    if (node >= NN) return;
    const float* xin = (sel == 0) ? xext : (sel == 1 ? g_X1 : g_X2);
    const float4* __restrict__ X4 = (const float4*)xin;
    int s = g_rowptr[node], e = g_rowptr[node + 1];
    float4 a0 = make_float4(0.f, 0.f, 0.f, 0.f);
    float4 a1 = make_float4(0.f, 0.f, 0.f, 0.f);
    int p = s;
    for (; p + 1 < e; p += 2) {
        int c0 = g_col[p], c1 = g_col[p + 1];
        float4 v0 = X4[(size_t)c0 * 32 + lane];
        float4 v1 = X4[(size_t)c1 * 32 + lane];
        a0.x += v0.x; a0.y += v0.y; a0.z += v0.z; a0.w += v0.w;
        a1.x += v1.x; a1.y += v1.y; a1.z += v1.z; a1.w += v1.w;
    }
    if (p < e) {
        int c0 = g_col[p];
        float4 v0 = X4[(size_t)c0 * 32 + lane];
        a0.x += v0.x; a0.y += v0.y; a0.z += v0.z; a0.w += v0.w;
    }
    float4 acc = make_float4(a0.x + a1.x, a0.y + a1.y, a0.z + a1.z, a0.w + a1.w);

    __nv_bfloat16 h0, h1, h2, h3, l0, l1, l2, l3;
    split2(acc.x, h0, l0); split2(acc.y, h1, l1);
    split2(acc.z, h2, l2); split2(acc.w, h3, l3);
    size_t base = (size_t)node * KZ + lane * 4;
    *(uint2*)&g_Zh[base] = make_uint2(pk(h0, h1), pk(h2, h3));
    *(uint2*)&g_Zl[base] = make_uint2(pk(l0, l1), pk(l2, l3));

    float dg = g_degf[node];
    float4 xv = X4[(size_t)node * 32 + lane];
    split2(dg * xv.x, h0, l0); split2(dg * xv.y, h1, l1);
    split2(dg * xv.z, h2, l2); split2(dg * xv.w, h3, l3);
    size_t base2 = (size_t)node * KZ + 128 + lane * 4;
    *(uint2*)&g_Zh[base2] = make_uint2(pk(h0, h1), pk(h2, h3));
    *(uint2*)&g_Zl[base2] = make_uint2(pk(l0, l1), pk(l2, l3));
}

// ---------------- per-layer GEMM: Y = leaky(Z @ W^T + deg*b), bf16-split mma
// Synchronous staging (proven 692us structure), pre-split W (bf16 direct copy).
// BM=128, BN=128, BK=32, 8 warps (4m x 2n), warp tile 32x64.
__global__ __launch_bounds__(256) void k_gemm(
    int layer, const float* __restrict__ bvec,
    float* __restrict__ oext, int osel, int last)
{
    __shared__ __nv_bfloat16 Ah[128 * SK], Al[128 * SK];
    __shared__ __nv_bfloat16 Bh[128 * SK], Bl[128 * SK];
    __shared__ float sb[128];
    const __nv_bfloat16* Wh = g_Wh + (size_t)layer * HD * KZ;
    const __nv_bfloat16* Wl = g_Wl + (size_t)layer * HD * KZ;

    int t = threadIdx.x;
    int lane = t & 31, wid = t >> 5;
    int wm = wid >> 1, wn = wid & 1;
    int m0 = blockIdx.x * 128;
    float* out = (osel == 3) ? oext : (osel == 1 ? g_X1 : g_X2);
    if (t < 128) sb[t] = bvec[t];

    float c[2][8][4];
    #pragma unroll
    for (int a = 0; a < 2; a++)
        #pragma unroll
        for (int b = 0; b < 8; b++)
            #pragma unroll
            for (int d = 0; d < 4; d++) c[a][b][d] = 0.f;

    for (int k0 = 0; k0 < KZ; k0 += 32) {
        #pragma unroll
        for (int h = 0; h < 2; h++) {
            int fid = t + h * 256;       // 0..511
            int row = fid >> 2, cc = fid & 3;
            int m = m0 + row;
            uint4 vh = make_uint4(0, 0, 0, 0), vl = make_uint4(0, 0, 0, 0);
            if (m < NN) {
                vh = *(const uint4*)&g_Zh[(size_t)m * KZ + k0 + cc * 8];
                vl = *(const uint4*)&g_Zl[(size_t)m * KZ + k0 + cc * 8];
            }
            *(uint4*)&Ah[row * SK + cc * 8] = vh;
            *(uint4*)&Al[row * SK + cc * 8] = vl;
            *(uint4*)&Bh[row * SK + cc * 8] =
                *(const uint4*)&Wh[(size_t)row * KZ + k0 + cc * 8];
            *(uint4*)&Bl[row * SK + cc * 8] =
                *(const uint4*)&Wl[(size_t)row * KZ + k0 + cc * 8];
        }
        __syncthreads();

        #pragma unroll
        for (int kk = 0; kk < 2; kk++) {
            uint32_t ah[2][4], al[2][4];
            #pragma unroll
            for (int mt = 0; mt < 2; mt++) {
                int r = wm * 32 + mt * 16 + (lane & 15);
                int kc = kk * 16 + ((lane >> 4) << 3);
                ldsm4(ah[mt], &Ah[r * SK + kc]);
                ldsm4(al[mt], &Al[r * SK + kc]);
            }
            #pragma unroll
            for (int p = 0; p < 4; p++) {
                int nr = wn * 64 + p * 16 + (lane & 7) + ((lane >> 4) << 3);
                int kc = kk * 16 + (((lane >> 3) & 1) << 3);
                uint32_t bh[4], bl[4];
                ldsm4(bh, &Bh[nr * SK + kc]);
                ldsm4(bl, &Bl[nr * SK + kc]);
                #pragma unroll
                for (int mt = 0; mt < 2; mt++) {
                    mma16816(c[mt][2 * p],     ah[mt], bh);
                    mma16816(c[mt][2 * p + 1], ah[mt], bh + 2);
                    mma16816(c[mt][2 * p],     ah[mt], bl);
                    mma16816(c[mt][2 * p + 1], ah[mt], bl + 2);
                    mma16816(c[mt][2 * p],     al[mt], bh);
                    mma16816(c[mt][2 * p + 1], al[mt], bh + 2);
                }
            }
        }
        __syncthreads();
    }

    // epilogue: y = c + deg*b, leaky (x2 if last)
    #pragma unroll
    for (int mt = 0; mt < 2; mt++) {
        int r0 = m0 + wm * 32 + mt * 16 + (lane >> 2);
        int r1 = r0 + 8;
        float dg0 = (r0 < NN) ? g_degf[r0] : 0.f;
        float dg1 = (r1 < NN) ? g_degf[r1] : 0.f;
        #pragma unroll
        for (int nt = 0; nt < 8; nt++) {
            int col = wn * 64 + nt * 8 + ((lane & 3) << 1);
            float b0 = sb[col], b1 = sb[col + 1];
            if (r0 < NN) {
                float y0 = c[mt][nt][0] + dg0 * b0;
                float y1 = c[mt][nt][1] + dg0 * b1;
                y0 = y0 > 0.f ? y0 : 0.01f * y0;
                y1 = y1 > 0.f ? y1 : 0.01f * y1;
                if (last) {
                    y0 = y0 > 0.f ? y0 : 0.01f * y0;
                    y1 = y1 > 0.f ? y1 : 0.01f * y1;
                }
                *(float2*)&out[(size_t)r0 * HD + col] = make_float2(y0, y1);
            }
            if (r1 < NN) {
                float y2 = c[mt][nt][2] + dg1 * b0;
                float y3 = c[mt][nt][3] + dg1 * b1;
                y2 = y2 > 0.f ? y2 : 0.01f * y2;
                y3 = y3 > 0.f ? y3 : 0.01f * y3;
                if (last) {
                    y2 = y2 > 0.f ? y2 : 0.01f * y2;
                    y3 = y3 > 0.f ? y3 : 0.01f * y3;
                }
                *(float2*)&out[(size_t)r1 * HD + col] = make_float2(y2, y3);
            }
        }
    }
}

// ---------------- launch ----------------
extern "C" void kernel_launch(void* const* d_in, const int* in_sizes, int n_in,
                              void* d_out, int out_size) {
    const float* x  = nullptr;
    const void*  ei = nullptr;
    const float* ea = nullptr;
    const float* Wm = nullptr;
    const float* bm = nullptr;
    for (int i = 0; i < n_in; i++) {
        switch (in_sizes[i]) {
            case 12800000: x  = (const float*)d_in[i]; break;
            case 1600000:  ei = d_in[i];               break;
            case 25600000: ea = (const float*)d_in[i]; break;
            case 110592:   Wm = (const float*)d_in[i]; break;
            case 384:      bm = (const float*)d_in[i]; break;
            default: break;
        }
    }
    float* out = (float*)d_out;

    const int nblk = (NN + 1023) / 1024;   // 98
    k_detect<<<1, 1>>>((const int*)ei);
    k_zero_deg<<<(NN + 255) / 256, 256>>>();
    k_hist<<<(NE + 255) / 256, 256>>>(ei);
    k_scan1<<<nblk, 1024>>>();
    k_scan2<<<1, 1>>>(nblk);
    k_scan3<<<(NN + 255) / 256, 256>>>();
    k_fill<<<(NE + 255) / 256, 256>>>(ei);
    k_pre<<<(NN * 32 + 255) / 256, 256>>>(ea);
    k_wsplit<<<(3 * HD * KZ + 255) / 256, 256>>>(Wm);

    const int gemm_blocks = (NN + 127) / 128;   // 782
    // layer 0: in = x,    out = g_X1
    k_spmm<<<(NN * 32 + 255) / 256, 256>>>(x, 0);
    k_gemm<<<gemm_blocks, 256>>>(0, bm + 0 * HD, out, 1, 0);
    // layer 1: in = g_X1, out = g_X2
    k_spmm<<<(NN * 32 + 255) / 256, 256>>>(nullptr, 1);
    k_gemm<<<gemm_blocks, 256>>>(1, bm + 1 * HD, out, 2, 0);
    // layer 2: in = g_X2, out = d_out (double leaky: activate_last)
    k_spmm<<<(NN * 32 + 255) / 256, 256>>>(nullptr, 2);
    k_gemm<<<gemm_blocks, 256>>>(2, bm + 2 * HD, out, 3, 1);
}